// round 12
// baseline (speedup 1.0000x reference)
#include <cuda_runtime.h>

// Problem constants (fixed shapes)
#define Dd 64
#define TE 128         // rows per block tile
#define NMAX 50000
#define EMAX 500000
#define EPS 1e-5f

typedef unsigned long long u64;

// ---------------- device scratch (static, no allocation) ----------------
__device__ __align__(16) float g_h[NMAX * Dd];
__device__ __align__(16) float g_aggr[NMAX * Dd];
__device__ __align__(16) float g_u[NMAX * Dd];
__device__ __align__(16) float g_m[(size_t)EMAX * Dd];
__device__ __align__(16) double g_sum[Dd];
__device__ __align__(16) double g_sumsq[Dd];
__device__ __align__(16) float g_scale[Dd];
__device__ __align__(16) float g_shift[Dd];
__device__ int g_done;   // zero-init; reset by last block each use

// ---------------- f32x2 helpers ----------------
__device__ __forceinline__ u64 pack2(float lo, float hi) {
    u64 r; asm("mov.b64 %0, {%1,%2};" : "=l"(r) : "f"(lo), "f"(hi)); return r;
}
__device__ __forceinline__ void unpack2(u64 v, float& lo, float& hi) {
    asm("mov.b64 {%0,%1}, %2;" : "=f"(lo), "=f"(hi) : "l"(v));
}
__device__ __forceinline__ void ffma2(u64& d, u64 a, u64 b) {
    asm("fma.rn.f32x2 %0, %1, %2, %0;" : "+l"(d) : "l"(a), "l"(b));
}
__device__ __forceinline__ void fadd2(u64& d, u64 a) {
    asm("add.rn.f32x2 %0, %0, %1;" : "+l"(d) : "l"(a));
}
__device__ __forceinline__ void fsq2(u64& d, u64 a) {
    asm("fma.rn.f32x2 %0, %1, %1, %0;" : "+l"(d) : "l"(a));
}

// ---------------- cp.async helpers ----------------
__device__ __forceinline__ void cp_async16(unsigned saddr, const void* gaddr) {
    asm volatile("cp.async.cg.shared.global [%0], [%1], 16;" :: "r"(saddr), "l"(gaddr));
}
__device__ __forceinline__ void cp_commit() {
    asm volatile("cp.async.commit_group;");
}
__device__ __forceinline__ void cp_wait_all() {
    asm volatile("cp.async.wait_group 0;");
}

// ---------------- fused BN finalize (last block of producer GEMM) ----------------
// All blocks: stats atomics -> fence -> sync -> ticket. Last block computes
// scale/shift, zeroes accumulators, resets ticket. Deterministic per replay.
__device__ __forceinline__ void bn_finalize_tail(
    int tid, const float* __restrict__ g, const float* __restrict__ be,
    double invCount, int* sLast) {
    __threadfence();
    __syncthreads();
    if (tid == 0) *sLast = (atomicAdd(&g_done, 1) == (int)gridDim.x - 1) ? 1 : 0;
    __syncthreads();
    if (*sLast) {
        __threadfence();
        if (tid < 64) {
            double s = g_sum[tid], q = g_sumsq[tid];
            double m = s * invCount;
            double var = q * invCount - m * m;
            if (var < 0.0) var = 0.0;
            float rstd = rsqrtf((float)var + EPS);
            float sc = g[tid] * rstd;
            g_scale[tid] = sc;
            g_shift[tid] = be[tid] - (float)m * sc;
            g_sum[tid] = 0.0;
            g_sumsq[tid] = 0.0;
        }
        if (tid == 0) g_done = 0;
    }
}

// ---------------- init: h = relu(x@Win + bin + prev@Whist + bhist) ----------------
__global__ void init_h_kernel(const float* __restrict__ x, const float* __restrict__ prev,
                              const float* __restrict__ wi, const float* __restrict__ bi,
                              const float* __restrict__ wh, const float* __restrict__ bh,
                              int N) {
    int i = blockIdx.x * blockDim.x + threadIdx.x;
    if (i >= N * Dd) return;
    int n = i >> 6, c = i & 63;
    float acc = bi[c] + bh[c];
    const float* xr = x + n * 11;
#pragma unroll
    for (int k = 0; k < 11; k++) acc = fmaf(xr[k], wi[k * Dd + c], acc);
    const float* pr = prev + n * Dd;
#pragma unroll 8
    for (int k = 0; k < Dd; k++) acc = fmaf(pr[k], wh[k * Dd + c], acc);
    g_h[i] = fmaxf(acc, 0.f);
}

// ======== Template A: single-buffer GEMM+BN+finalize, MODE 0 (K=132) / MODE 2 (K=128) ========
template <int K, int MODE>
__global__ __launch_bounds__(128)
void gemm_bn_kernel(const float* __restrict__ W, const float* __restrict__ bias,
                    const float* __restrict__ inA, const float* __restrict__ inB,
                    const int* __restrict__ dstIdx, const int* __restrict__ srcIdx,
                    const float* __restrict__ gamma, const float* __restrict__ beta,
                    double invCount,
                    float* __restrict__ out, int M) {
    constexpr int Kv4 = K / 4;
    constexpr int Kv4p = Kv4 + 1;   // padded row stride (float4 units)

    extern __shared__ float smem[];
    float4* sIn4 = (float4*)smem;                          // TE * Kv4p float4
    float*  sW   = smem + TE * Kv4p * 4;                   // K * 64 floats
    double* sSum = (double*)(sW + K * 64);                 // 64
    double* sSq  = sSum + 64;                              // 64
    int* sDst = (int*)(sSq + 64);                          // 128
    int* sSrc = sDst + 128;                                // 128
    int* sLast = sSrc + 128;                               // 1

    const int tid = threadIdx.x;
    const int cg = tid & 7;
    const int cBase = cg * 8;            // 8 output cols per thread
    const int egrp = tid >> 3;           // 0..15
    const int band = (egrp >> 2) << 5;   // 32-row band
    const int elane = egrp & 3;          // stride-4 interleave

    {
        const float4* W4 = (const float4*)W;
        float4* sW4 = (float4*)sW;
        for (int i = tid; i < K * 16; i += 128) sW4[i] = W4[i];
    }
    if (tid < 64) { sSum[tid] = 0.0; sSq[tid] = 0.0; }

    u64 bb[4];
    {
        const ulonglong2* bp = (const ulonglong2*)(bias + cBase);
        ulonglong2 t0 = bp[0], t1 = bp[1];
        bb[0] = t0.x; bb[1] = t0.y; bb[2] = t1.x; bb[3] = t1.y;
    }

    u64 ls[4] = {0, 0, 0, 0}, lq[4] = {0, 0, 0, 0};

    const float4* inA4 = (const float4*)inA;
    const float4* inB4 = (const float4*)inB;

    const int nTiles = (M + TE - 1) / TE;
    for (int tile = blockIdx.x; tile < nTiles; tile += gridDim.x) {
        const int base = tile * TE;

        if (MODE == 0) {
            int ge = base + tid;
            bool ok = ge < M;
            sDst[tid] = ok ? dstIdx[ge] : 0;
            sSrc[tid] = ok ? srcIdx[ge] : 0;
        }
        __syncthreads();

        for (int idx = tid; idx < TE * Kv4; idx += 128) {
            int e = idx / Kv4;
            int kq = idx - e * Kv4;
            int ge = base + e;
            float4 v = make_float4(0.f, 0.f, 0.f, 0.f);
            if (ge < M) {
                if (MODE == 0) {
                    if (kq < 16)      v = inA4[(size_t)sDst[e] * 16 + kq];
                    else if (kq < 32) v = inA4[(size_t)sSrc[e] * 16 + (kq - 16)];
                    else              v = inB4[ge];
                } else {  // MODE 2
                    if (kq < 16) v = inA4[(size_t)ge * 16 + kq];
                    else         v = inB4[(size_t)ge * 16 + (kq - 16)];
                }
            }
            sIn4[e * Kv4p + kq] = v;
        }
        __syncthreads();

        u64 acc[8][4];
#pragma unroll
        for (int i = 0; i < 8; i++) {
            acc[i][0] = bb[0]; acc[i][1] = bb[1]; acc[i][2] = bb[2]; acc[i][3] = bb[3];
        }

#pragma unroll 1
        for (int kq = 0; kq < Kv4; kq++) {
            float4 a4[8];
#pragma unroll
            for (int i = 0; i < 8; i++)
                a4[i] = sIn4[(band + elane + (i << 2)) * Kv4p + kq];
#pragma unroll
            for (int kr = 0; kr < 4; kr++) {
                const int k = kq * 4 + kr;
                const ulonglong2* wp = (const ulonglong2*)(sW + k * 64 + cBase);
                ulonglong2 w01 = wp[0];
                ulonglong2 w23 = wp[1];
#pragma unroll
                for (int i = 0; i < 8; i++) {
                    float av = (kr == 0) ? a4[i].x : (kr == 1) ? a4[i].y
                             : (kr == 2) ? a4[i].z : a4[i].w;
                    u64 ap = pack2(av, av);
                    ffma2(acc[i][0], ap, w01.x);
                    ffma2(acc[i][1], ap, w01.y);
                    ffma2(acc[i][2], ap, w23.x);
                    ffma2(acc[i][3], ap, w23.y);
                }
            }
        }

#pragma unroll
        for (int i = 0; i < 8; i++) {
            int e = band + elane + (i << 2);
            int ge = base + e;
            if (ge < M) {
                ulonglong2* o = (ulonglong2*)(out + (size_t)ge * Dd + cBase);
                ulonglong2 s0; s0.x = acc[i][0]; s0.y = acc[i][1];
                ulonglong2 s1; s1.x = acc[i][2]; s1.y = acc[i][3];
                o[0] = s0; o[1] = s1;
#pragma unroll
                for (int p = 0; p < 4; p++) { fadd2(ls[p], acc[i][p]); fsq2(lq[p], acc[i][p]); }
            }
        }
        __syncthreads();
    }

#pragma unroll
    for (int p = 0; p < 4; p++) {
        float lo, hi;
        unpack2(ls[p], lo, hi);
        atomicAdd(&sSum[cBase + 2 * p], (double)lo);
        atomicAdd(&sSum[cBase + 2 * p + 1], (double)hi);
        unpack2(lq[p], lo, hi);
        atomicAdd(&sSq[cBase + 2 * p], (double)lo);
        atomicAdd(&sSq[cBase + 2 * p + 1], (double)hi);
    }
    __syncthreads();
    if (tid < 64) {
        atomicAdd(&g_sum[tid], sSum[tid]);
        atomicAdd(&g_sumsq[tid], sSq[tid]);
    }
    bn_finalize_tail(tid, gamma, beta, invCount, sLast);
}

// ======== Template B: cp.async double-buffer GEMM+BN+finalize, K=64 affine+relu input ========
__global__ __launch_bounds__(128)
void gemm_bn_pipe_kernel(const float* __restrict__ W, const float* __restrict__ bias,
                         const float* __restrict__ inA,
                         const float* __restrict__ scale, const float* __restrict__ shift,
                         const float* __restrict__ gamma, const float* __restrict__ beta,
                         double invCount,
                         float* __restrict__ out, int M) {
    constexpr int K = 64;
    constexpr int Kv4 = K / 4;        // 16
    constexpr int Kv4p = Kv4 + 1;     // 17
    constexpr int BUF = TE * Kv4p;

    extern __shared__ float4 smem4[];
    float4* sIn4 = smem4;                              // 2 * BUF
    float*  sW   = (float*)(smem4 + 2 * BUF);          // K * 64
    float*  sB   = sW + K * 64;                        // 64
    float*  sScale = sB + 64;                          // 64
    float*  sShift = sScale + 64;                      // 64
    double* sSum = (double*)(sShift + 64);             // 64
    double* sSq  = sSum + 64;                          // 64
    int* sLast = (int*)(sSq + 64);                     // 1

    const int tid = threadIdx.x;
    const int cg = tid & 7;
    const int cBase = cg * 8;
    const int egrp = tid >> 3;
    const int band = (egrp >> 2) << 5;
    const int elane = egrp & 3;

    {
        const float4* W4 = (const float4*)W;
        float4* sW4 = (float4*)sW;
        for (int i = tid; i < K * 16; i += 128) sW4[i] = W4[i];
    }
    if (tid < 16) ((float4*)sB)[tid] = ((const float4*)bias)[tid];
    if (tid < 64) { sScale[tid] = scale[tid]; sShift[tid] = shift[tid]; }
    if (tid < 64) { sSum[tid] = 0.0; sSq[tid] = 0.0; }

    const unsigned sInBase = (unsigned)__cvta_generic_to_shared(sIn4);
    const float4* inA4 = (const float4*)inA;

    auto stage = [&](int base, int b) {
        const unsigned bufAddr = sInBase + (unsigned)b * BUF * 16u;
        for (int idx = tid; idx < TE * Kv4; idx += 128) {
            int e = idx >> 4;
            int kq = idx & 15;
            int ge = base + e;
            unsigned sa = bufAddr + (unsigned)(e * Kv4p + kq) * 16u;
            if (ge < M) {
                cp_async16(sa, inA4 + (size_t)ge * 16 + kq);
            } else {
                sIn4[b * BUF + e * Kv4p + kq] = make_float4(0.f, 0.f, 0.f, 0.f);
            }
        }
        cp_commit();
    };

    u64 bb[4];
    u64 ls[4] = {0, 0, 0, 0}, lq[4] = {0, 0, 0, 0};

    const int nTiles = (M + TE - 1) / TE;
    const int stride = gridDim.x;
    int t = blockIdx.x;
    int buf = 0;
    bool first = true;

    if (t < nTiles) stage(t * TE, 0);

    for (; t < nTiles; t += stride) {
        cp_wait_all();
        __syncthreads();

        if (first) {
            const ulonglong2* bp = (const ulonglong2*)(sB + cBase);
            ulonglong2 t0 = bp[0], t1 = bp[1];
            bb[0] = t0.x; bb[1] = t0.y; bb[2] = t1.x; bb[3] = t1.y;
            first = false;
        }

        if (t + stride < nTiles) stage((t + stride) * TE, buf ^ 1);

        // in-smem affine+relu transform
        {
            float4* bufp = sIn4 + buf * BUF;
            const float4* sc4 = (const float4*)sScale;
            const float4* sh4 = (const float4*)sShift;
            for (int idx = tid; idx < TE * Kv4; idx += 128) {
                int e = idx >> 4;
                int kq = idx & 15;
                float4 v = bufp[e * Kv4p + kq];
                float4 sc = sc4[kq], sh = sh4[kq];
                v.x = fmaxf(fmaf(v.x, sc.x, sh.x), 0.f);
                v.y = fmaxf(fmaf(v.y, sc.y, sh.y), 0.f);
                v.z = fmaxf(fmaf(v.z, sc.z, sh.z), 0.f);
                v.w = fmaxf(fmaf(v.w, sc.w, sh.w), 0.f);
                bufp[e * Kv4p + kq] = v;
            }
            __syncthreads();
        }

        const float4* bufp = sIn4 + buf * BUF;
        const int base = t * TE;

        u64 acc[8][4];
#pragma unroll
        for (int i = 0; i < 8; i++) {
            acc[i][0] = bb[0]; acc[i][1] = bb[1]; acc[i][2] = bb[2]; acc[i][3] = bb[3];
        }

#pragma unroll 1
        for (int kq = 0; kq < Kv4; kq++) {
            float4 a4[8];
#pragma unroll
            for (int i = 0; i < 8; i++)
                a4[i] = bufp[(band + elane + (i << 2)) * Kv4p + kq];
#pragma unroll
            for (int kr = 0; kr < 4; kr++) {
                const int k = kq * 4 + kr;
                const ulonglong2* wp = (const ulonglong2*)(sW + k * 64 + cBase);
                ulonglong2 w01 = wp[0];
                ulonglong2 w23 = wp[1];
#pragma unroll
                for (int i = 0; i < 8; i++) {
                    float av = (kr == 0) ? a4[i].x : (kr == 1) ? a4[i].y
                             : (kr == 2) ? a4[i].z : a4[i].w;
                    u64 ap = pack2(av, av);
                    ffma2(acc[i][0], ap, w01.x);
                    ffma2(acc[i][1], ap, w01.y);
                    ffma2(acc[i][2], ap, w23.x);
                    ffma2(acc[i][3], ap, w23.y);
                }
            }
        }

#pragma unroll
        for (int i = 0; i < 8; i++) {
            int e = band + elane + (i << 2);
            int ge = base + e;
            if (ge < M) {
                ulonglong2* o = (ulonglong2*)(out + (size_t)ge * Dd + cBase);
                ulonglong2 s0; s0.x = acc[i][0]; s0.y = acc[i][1];
                ulonglong2 s1; s1.x = acc[i][2]; s1.y = acc[i][3];
                o[0] = s0; o[1] = s1;
#pragma unroll
                for (int p = 0; p < 4; p++) { fadd2(ls[p], acc[i][p]); fsq2(lq[p], acc[i][p]); }
            }
        }
        buf ^= 1;
    }

    __syncthreads();
#pragma unroll
    for (int p = 0; p < 4; p++) {
        float lo, hi;
        unpack2(ls[p], lo, hi);
        atomicAdd(&sSum[cBase + 2 * p], (double)lo);
        atomicAdd(&sSum[cBase + 2 * p + 1], (double)hi);
        unpack2(lq[p], lo, hi);
        atomicAdd(&sSq[cBase + 2 * p], (double)lo);
        atomicAdd(&sSq[cBase + 2 * p + 1], (double)hi);
    }
    __syncthreads();
    if (tid < 64) {
        atomicAdd(&g_sum[tid], sSum[tid]);
        atomicAdd(&g_sumsq[tid], sSq[tid]);
    }
    bn_finalize_tail(tid, gamma, beta, invCount, sLast);
}

// ---------------- zero aggr ----------------
__global__ void zero_aggr_kernel(int total4) {
    int i = blockIdx.x * blockDim.x + threadIdx.x;
    if (i < total4) ((float4*)g_aggr)[i] = make_float4(0.f, 0.f, 0.f, 0.f);
}

// ---------------- scatter: aggr[dst] += relu(affine(m2)), vectorized red ----------------
__global__ void scatter_kernel(const float* __restrict__ m, const int* __restrict__ dst,
                               const float* __restrict__ scale, const float* __restrict__ shift,
                               int E) {
    int idx = blockIdx.x * blockDim.x + threadIdx.x;
    int total = E * 4;
    if (idx >= total) return;
    int e = idx >> 2, q = idx & 3;        // q: 16-float quarter of the row
    const float4* m4 = (const float4*)m + (size_t)e * 16 + q * 4;
    const float4* sc4 = (const float4*)scale + q * 4;
    const float4* sh4 = (const float4*)shift + q * 4;
    float* a = g_aggr + (size_t)dst[e] * Dd + q * 16;
#pragma unroll
    for (int j = 0; j < 4; j++) {
        float4 v = m4[j];
        float4 sc = sc4[j], sh = sh4[j];
        float r0 = fmaxf(fmaf(v.x, sc.x, sh.x), 0.f);
        float r1 = fmaxf(fmaf(v.y, sc.y, sh.y), 0.f);
        float r2 = fmaxf(fmaf(v.z, sc.z, sh.z), 0.f);
        float r3 = fmaxf(fmaf(v.w, sc.w, sh.w), 0.f);
        asm volatile("red.global.add.v4.f32 [%0], {%1, %2, %3, %4};"
                     :: "l"(a + j * 4), "f"(r0), "f"(r1), "f"(r2), "f"(r3) : "memory");
    }
}

// ---------------- h += relu(affine(u2)); optionally also emit h to out (last layer) ----------------
__global__ void h_update_kernel(const float* __restrict__ u, const float* __restrict__ scale,
                                const float* __restrict__ shift, float* __restrict__ outh,
                                int total4) {
    int i = blockIdx.x * blockDim.x + threadIdx.x;
    if (i >= total4) return;
    int q = i & 15;
    float4 v = ((const float4*)u)[i];
    float4 sc = ((const float4*)scale)[q];
    float4 sh = ((const float4*)shift)[q];
    float4 hv = ((float4*)g_h)[i];
    hv.x += fmaxf(fmaf(v.x, sc.x, sh.x), 0.f);
    hv.y += fmaxf(fmaf(v.y, sc.y, sh.y), 0.f);
    hv.z += fmaxf(fmaf(v.z, sc.z, sh.z), 0.f);
    hv.w += fmaxf(fmaf(v.w, sc.w, sh.w), 0.f);
    ((float4*)g_h)[i] = hv;
    if (outh) {   // scalar stores: outh is not 16B-aligned (d_out + 250001 floats)
        float* o = outh + (size_t)i * 4;
        o[0] = hv.x; o[1] = hv.y; o[2] = hv.z; o[3] = hv.w;
    }
}

// ---------------- column sums of h ----------------
__global__ void colsum_kernel(int N) {
    __shared__ double s[Dd];
    int tid = threadIdx.x;
    if (tid < Dd) s[tid] = 0.0;
    __syncthreads();
    int c = tid & 63;
    int rowsPerBlk = blockDim.x >> 6;
    float part = 0.f;
    for (int n = blockIdx.x * rowsPerBlk + (tid >> 6); n < N; n += gridDim.x * rowsPerBlk)
        part += g_h[(size_t)n * Dd + c];
    atomicAdd(&s[c], (double)part);
    __syncthreads();
    if (tid < Dd) atomicAdd(&g_sum[tid], s[tid]);
}

__global__ void graph_out_kernel(const float* __restrict__ gw, const float* __restrict__ gb,
                                 float* __restrict__ out, double invN) {
    __shared__ float partial[Dd];
    int c = threadIdx.x;
    if (c < Dd) {
        partial[c] = (float)(g_sum[c] * invN) * gw[c];
        g_sum[c] = 0.0;
    }
    __syncthreads();
    if (c == 0) {
        float s = 0.f;
        for (int i = 0; i < Dd; i++) s += partial[i];
        out[0] = s + gb[0];
    }
}

__global__ void node_out_kernel(const float* __restrict__ nw, const float* __restrict__ nb,
                                float* __restrict__ out, int N) {
    int idx = blockIdx.x * blockDim.x + threadIdx.x;
    if (idx >= N * 5) return;
    int n = idx / 5, o = idx - n * 5;
    float acc = nb[o];
    const float* hr = g_h + (size_t)n * Dd;
#pragma unroll 8
    for (int k = 0; k < Dd; k++) acc = fmaf(hr[k], nw[k * 5 + o], acc);
    out[idx] = acc;
}

// ---------------- host launcher ----------------
extern "C" void kernel_launch(void* const* d_in, const int* in_sizes, int n_in,
                              void* d_out, int out_size) {
    const float* x       = (const float*)d_in[0];
    const int*   ei      = (const int*)d_in[1];
    const float* eattr   = (const float*)d_in[2];
    const float* prev_h  = (const float*)d_in[3];
    const float* lin_in_w = (const float*)d_in[4];
    const float* lin_in_b = (const float*)d_in[5];
    const float* hist_w   = (const float*)d_in[6];
    const float* hist_b   = (const float*)d_in[7];
    const float* msg_w1 = (const float*)d_in[8];
    const float* msg_b1 = (const float*)d_in[9];
    const float* msg_g1 = (const float*)d_in[10];
    const float* msg_be1 = (const float*)d_in[11];
    const float* msg_w2 = (const float*)d_in[12];
    const float* msg_b2 = (const float*)d_in[13];
    const float* msg_g2 = (const float*)d_in[14];
    const float* msg_be2 = (const float*)d_in[15];
    const float* upd_w1 = (const float*)d_in[16];
    const float* upd_b1 = (const float*)d_in[17];
    const float* upd_g1 = (const float*)d_in[18];
    const float* upd_be1 = (const float*)d_in[19];
    const float* upd_w2 = (const float*)d_in[20];
    const float* upd_b2 = (const float*)d_in[21];
    const float* upd_g2 = (const float*)d_in[22];
    const float* upd_be2 = (const float*)d_in[23];
    const float* graph_w = (const float*)d_in[24];
    const float* graph_b = (const float*)d_in[25];
    const float* node_w  = (const float*)d_in[26];
    const float* node_b  = (const float*)d_in[27];

    const int N = in_sizes[0] / 11;
    const int E = in_sizes[1] / 2;
    const int* src = ei;
    const int* dst = ei + E;

    float* out = (float*)d_out;
    float* out_graph = out;
    float* out_node = out + 1;
    float* out_h = out + 1 + (size_t)N * 5;

    float *p_h, *p_aggr, *p_u, *p_m, *p_scale, *p_shift;
    cudaGetSymbolAddress((void**)&p_h, g_h);
    cudaGetSymbolAddress((void**)&p_aggr, g_aggr);
    cudaGetSymbolAddress((void**)&p_u, g_u);
    cudaGetSymbolAddress((void**)&p_m, g_m);
    cudaGetSymbolAddress((void**)&p_scale, g_scale);
    cudaGetSymbolAddress((void**)&p_shift, g_shift);

    // Template A: TE*(K/4+1)*16 + K*256 + 1024(stats) + 1024(idx) + 16(flag)
    const int s132 = TE * 34 * 16 + 132 * 256 + 1024 + 1024 + 16;
    const int s128 = TE * 33 * 16 + 128 * 256 + 1024 + 1024 + 16;
    // Template B: 2*TE*17*16 + (64*64+192)*4 + 1024 + 16(flag)
    const int s64  = 2 * TE * 17 * 16 + (64 * 64 + 192) * 4 + 1024 + 16;
    cudaFuncSetAttribute(gemm_bn_kernel<132, 0>, cudaFuncAttributeMaxDynamicSharedMemorySize, s132);
    cudaFuncSetAttribute(gemm_bn_kernel<128, 2>, cudaFuncAttributeMaxDynamicSharedMemorySize, s128);
    cudaFuncSetAttribute(gemm_bn_pipe_kernel,    cudaFuncAttributeMaxDynamicSharedMemorySize, s64);

    const int tilesE = (E + TE - 1) / TE;
    const int tilesN = (N + TE - 1) / TE;
    const int gE132 = tilesE < 296 ? tilesE : 296;   // 2 blocks/SM
    const int gE64  = tilesE < 296 ? tilesE : 296;
    const int gN128 = tilesN < 296 ? tilesN : 296;
    const int gN64  = tilesN < 296 ? tilesN : 296;

    const double invE = 1.0 / (double)E;
    const double invN = 1.0 / (double)N;

    init_h_kernel<<<(N * Dd + 255) / 256, 256>>>(x, prev_h, lin_in_w, lin_in_b, hist_w, hist_b, N);

    for (int l = 0; l < 4; l++) {
        gemm_bn_kernel<132, 0><<<gE132, 128, s132>>>(
            msg_w1 + (size_t)l * 132 * Dd, msg_b1 + l * Dd,
            p_h, eattr, dst, src,
            msg_g1 + l * Dd, msg_be1 + l * Dd, invE, p_m, E);

        gemm_bn_pipe_kernel<<<gE64, 128, s64>>>(
            msg_w2 + (size_t)l * 64 * Dd, msg_b2 + l * Dd,
            p_m, p_scale, p_shift,
            msg_g2 + l * Dd, msg_be2 + l * Dd, invE, p_m, E);

        zero_aggr_kernel<<<(N * 16 + 255) / 256, 256>>>(N * 16);
        scatter_kernel<<<(E * 4 + 255) / 256, 256>>>(p_m, dst, p_scale, p_shift, E);

        gemm_bn_kernel<128, 2><<<gN128, 128, s128>>>(
            upd_w1 + (size_t)l * 128 * Dd, upd_b1 + l * Dd,
            p_h, p_aggr, nullptr, nullptr,
            upd_g1 + l * Dd, upd_be1 + l * Dd, invN, p_u, N);

        gemm_bn_pipe_kernel<<<gN64, 128, s64>>>(
            upd_w2 + (size_t)l * 64 * Dd, upd_b2 + l * Dd,
            p_u, p_scale, p_shift,
            upd_g2 + l * Dd, upd_be2 + l * Dd, invN, p_u, N);

        h_update_kernel<<<(N * 16 + 255) / 256, 256>>>(
            p_u, p_scale, p_shift, (l == 3) ? out_h : (float*)nullptr, N * 16);
    }

    colsum_kernel<<<444, 256>>>(N);
    graph_out_kernel<<<1, 64>>>(graph_w, graph_b, out_graph, invN);
    node_out_kernel<<<(N * 5 + 255) / 256, 256>>>(node_w, node_b, out_node, N);
}

// round 13
// speedup vs baseline: 1.0564x; 1.0564x over previous
#include <cuda_runtime.h>

// Problem constants (fixed shapes)
#define Dd 64
#define TE 128         // rows per block tile
#define NMAX 50000
#define EMAX 500000
#define EPS 1e-5f

typedef unsigned long long u64;

// ---------------- device scratch (static, no allocation) ----------------
__device__ __align__(16) float g_h[NMAX * Dd];
__device__ __align__(16) float g_aggr[NMAX * Dd];
__device__ __align__(16) float g_u[NMAX * Dd];
__device__ __align__(16) float g_m[(size_t)EMAX * Dd];
__device__ __align__(16) double g_sum[Dd];
__device__ __align__(16) double g_sumsq[Dd];
__device__ __align__(16) float g_scale[Dd];
__device__ __align__(16) float g_shift[Dd];

// ---------------- f32x2 helpers ----------------
__device__ __forceinline__ u64 pack2(float lo, float hi) {
    u64 r; asm("mov.b64 %0, {%1,%2};" : "=l"(r) : "f"(lo), "f"(hi)); return r;
}
__device__ __forceinline__ void unpack2(u64 v, float& lo, float& hi) {
    asm("mov.b64 {%0,%1}, %2;" : "=f"(lo), "=f"(hi) : "l"(v));
}
__device__ __forceinline__ void ffma2(u64& d, u64 a, u64 b) {
    asm("fma.rn.f32x2 %0, %1, %2, %0;" : "+l"(d) : "l"(a), "l"(b));
}
__device__ __forceinline__ void fadd2(u64& d, u64 a) {
    asm("add.rn.f32x2 %0, %0, %1;" : "+l"(d) : "l"(a));
}
__device__ __forceinline__ void fsq2(u64& d, u64 a) {
    asm("fma.rn.f32x2 %0, %1, %1, %0;" : "+l"(d) : "l"(a));
}

// ---------------- cp.async helpers ----------------
__device__ __forceinline__ void cp_async16(unsigned saddr, const void* gaddr) {
    asm volatile("cp.async.cg.shared.global [%0], [%1], 16;" :: "r"(saddr), "l"(gaddr));
}
__device__ __forceinline__ void cp_commit() {
    asm volatile("cp.async.commit_group;");
}
__device__ __forceinline__ void cp_wait_all() {
    asm volatile("cp.async.wait_group 0;");
}

// ---------------- init: h = relu(x@Win + bin + prev@Whist + bhist) ----------------
__global__ void init_h_kernel(const float* __restrict__ x, const float* __restrict__ prev,
                              const float* __restrict__ wi, const float* __restrict__ bi,
                              const float* __restrict__ wh, const float* __restrict__ bh,
                              int N) {
    int i = blockIdx.x * blockDim.x + threadIdx.x;
    if (i >= N * Dd) return;
    int n = i >> 6, c = i & 63;
    float acc = bi[c] + bh[c];
    const float* xr = x + n * 11;
#pragma unroll
    for (int k = 0; k < 11; k++) acc = fmaf(xr[k], wi[k * Dd + c], acc);
    const float* pr = prev + n * Dd;
#pragma unroll 8
    for (int k = 0; k < Dd; k++) acc = fmaf(pr[k], wh[k * Dd + c], acc);
    g_h[i] = fmaxf(acc, 0.f);
}

// ======== Template A: single-buffer GEMM+BN (R2-proven), MODE 0 (K=132) / MODE 2 (K=128) ========
template <int K, int MODE>
__global__ __launch_bounds__(128)
void gemm_bn_kernel(const float* __restrict__ W, const float* __restrict__ bias,
                    const float* __restrict__ inA, const float* __restrict__ inB,
                    const int* __restrict__ dstIdx, const int* __restrict__ srcIdx,
                    float* __restrict__ out, int M) {
    constexpr int Kv4 = K / 4;
    constexpr int Kv4p = Kv4 + 1;   // padded row stride (float4 units)

    extern __shared__ float smem[];
    float4* sIn4 = (float4*)smem;                          // TE * Kv4p float4
    float*  sW   = smem + TE * Kv4p * 4;                   // K * 64 floats
    double* sSum = (double*)(sW + K * 64);                 // 64
    double* sSq  = sSum + 64;                              // 64
    int* sDst = (int*)(sSq + 64);                          // 128
    int* sSrc = sDst + 128;                                // 128

    const int tid = threadIdx.x;
    const int cg = tid & 7;
    const int cBase = cg * 8;            // 8 output cols per thread
    const int egrp = tid >> 3;           // 0..15
    const int band = (egrp >> 2) << 5;   // 32-row band
    const int elane = egrp & 3;          // stride-4 interleave

    {
        const float4* W4 = (const float4*)W;
        float4* sW4 = (float4*)sW;
        for (int i = tid; i < K * 16; i += 128) sW4[i] = W4[i];
    }
    if (tid < 64) { sSum[tid] = 0.0; sSq[tid] = 0.0; }

    u64 bb[4];
    {
        const ulonglong2* bp = (const ulonglong2*)(bias + cBase);
        ulonglong2 t0 = bp[0], t1 = bp[1];
        bb[0] = t0.x; bb[1] = t0.y; bb[2] = t1.x; bb[3] = t1.y;
    }

    u64 ls[4] = {0, 0, 0, 0}, lq[4] = {0, 0, 0, 0};

    const float4* inA4 = (const float4*)inA;
    const float4* inB4 = (const float4*)inB;

    const int nTiles = (M + TE - 1) / TE;
    for (int tile = blockIdx.x; tile < nTiles; tile += gridDim.x) {
        const int base = tile * TE;

        if (MODE == 0) {
            int ge = base + tid;
            bool ok = ge < M;
            sDst[tid] = ok ? dstIdx[ge] : 0;
            sSrc[tid] = ok ? srcIdx[ge] : 0;
        }
        __syncthreads();

        for (int idx = tid; idx < TE * Kv4; idx += 128) {
            int e = idx / Kv4;
            int kq = idx - e * Kv4;
            int ge = base + e;
            float4 v = make_float4(0.f, 0.f, 0.f, 0.f);
            if (ge < M) {
                if (MODE == 0) {
                    if (kq < 16)      v = inA4[(size_t)sDst[e] * 16 + kq];
                    else if (kq < 32) v = inA4[(size_t)sSrc[e] * 16 + (kq - 16)];
                    else              v = inB4[ge];
                } else {  // MODE 2
                    if (kq < 16) v = inA4[(size_t)ge * 16 + kq];
                    else         v = inB4[(size_t)ge * 16 + (kq - 16)];
                }
            }
            sIn4[e * Kv4p + kq] = v;
        }
        __syncthreads();

        u64 acc[8][4];
#pragma unroll
        for (int i = 0; i < 8; i++) {
            acc[i][0] = bb[0]; acc[i][1] = bb[1]; acc[i][2] = bb[2]; acc[i][3] = bb[3];
        }

#pragma unroll 1
        for (int kq = 0; kq < Kv4; kq++) {
            float4 a4[8];
#pragma unroll
            for (int i = 0; i < 8; i++)
                a4[i] = sIn4[(band + elane + (i << 2)) * Kv4p + kq];
#pragma unroll
            for (int kr = 0; kr < 4; kr++) {
                const int k = kq * 4 + kr;
                const ulonglong2* wp = (const ulonglong2*)(sW + k * 64 + cBase);
                ulonglong2 w01 = wp[0];
                ulonglong2 w23 = wp[1];
#pragma unroll
                for (int i = 0; i < 8; i++) {
                    float av = (kr == 0) ? a4[i].x : (kr == 1) ? a4[i].y
                             : (kr == 2) ? a4[i].z : a4[i].w;
                    u64 ap = pack2(av, av);
                    ffma2(acc[i][0], ap, w01.x);
                    ffma2(acc[i][1], ap, w01.y);
                    ffma2(acc[i][2], ap, w23.x);
                    ffma2(acc[i][3], ap, w23.y);
                }
            }
        }

#pragma unroll
        for (int i = 0; i < 8; i++) {
            int e = band + elane + (i << 2);
            int ge = base + e;
            if (ge < M) {
                ulonglong2* o = (ulonglong2*)(out + (size_t)ge * Dd + cBase);
                ulonglong2 s0; s0.x = acc[i][0]; s0.y = acc[i][1];
                ulonglong2 s1; s1.x = acc[i][2]; s1.y = acc[i][3];
                o[0] = s0; o[1] = s1;
#pragma unroll
                for (int p = 0; p < 4; p++) { fadd2(ls[p], acc[i][p]); fsq2(lq[p], acc[i][p]); }
            }
        }
        __syncthreads();
    }

#pragma unroll
    for (int p = 0; p < 4; p++) {
        float lo, hi;
        unpack2(ls[p], lo, hi);
        atomicAdd(&sSum[cBase + 2 * p], (double)lo);
        atomicAdd(&sSum[cBase + 2 * p + 1], (double)hi);
        unpack2(lq[p], lo, hi);
        atomicAdd(&sSq[cBase + 2 * p], (double)lo);
        atomicAdd(&sSq[cBase + 2 * p + 1], (double)hi);
    }
    __syncthreads();
    if (tid < 64) {
        atomicAdd(&g_sum[tid], sSum[tid]);
        atomicAdd(&g_sumsq[tid], sSq[tid]);
    }
}

// ======== Template B: cp.async double-buffer GEMM+BN (R8-proven), K=64 affine+relu input ========
__global__ __launch_bounds__(128)
void gemm_bn_pipe_kernel(const float* __restrict__ W, const float* __restrict__ bias,
                         const float* __restrict__ inA,
                         const float* __restrict__ scale, const float* __restrict__ shift,
                         float* __restrict__ out, int M) {
    constexpr int K = 64;
    constexpr int Kv4 = K / 4;        // 16
    constexpr int Kv4p = Kv4 + 1;     // 17
    constexpr int BUF = TE * Kv4p;

    extern __shared__ float4 smem4[];
    float4* sIn4 = smem4;                              // 2 * BUF
    float*  sW   = (float*)(smem4 + 2 * BUF);          // K * 64
    float*  sB   = sW + K * 64;                        // 64
    float*  sScale = sB + 64;                          // 64
    float*  sShift = sScale + 64;                      // 64
    double* sSum = (double*)(sShift + 64);             // 64
    double* sSq  = sSum + 64;                          // 64

    const int tid = threadIdx.x;
    const int cg = tid & 7;
    const int cBase = cg * 8;
    const int egrp = tid >> 3;
    const int band = (egrp >> 2) << 5;
    const int elane = egrp & 3;

    {
        const float4* W4 = (const float4*)W;
        float4* sW4 = (float4*)sW;
        for (int i = tid; i < K * 16; i += 128) sW4[i] = W4[i];
    }
    if (tid < 16) ((float4*)sB)[tid] = ((const float4*)bias)[tid];
    if (tid < 64) { sScale[tid] = scale[tid]; sShift[tid] = shift[tid]; }
    if (tid < 64) { sSum[tid] = 0.0; sSq[tid] = 0.0; }

    const unsigned sInBase = (unsigned)__cvta_generic_to_shared(sIn4);
    const float4* inA4 = (const float4*)inA;

    auto stage = [&](int base, int b) {
        const unsigned bufAddr = sInBase + (unsigned)b * BUF * 16u;
        for (int idx = tid; idx < TE * Kv4; idx += 128) {
            int e = idx >> 4;
            int kq = idx & 15;
            int ge = base + e;
            unsigned sa = bufAddr + (unsigned)(e * Kv4p + kq) * 16u;
            if (ge < M) {
                cp_async16(sa, inA4 + (size_t)ge * 16 + kq);
            } else {
                sIn4[b * BUF + e * Kv4p + kq] = make_float4(0.f, 0.f, 0.f, 0.f);
            }
        }
        cp_commit();
    };

    u64 bb[4];
    u64 ls[4] = {0, 0, 0, 0}, lq[4] = {0, 0, 0, 0};

    const int nTiles = (M + TE - 1) / TE;
    const int stride = gridDim.x;
    int t = blockIdx.x;
    int buf = 0;
    bool first = true;

    if (t < nTiles) stage(t * TE, 0);

    for (; t < nTiles; t += stride) {
        cp_wait_all();
        __syncthreads();

        if (first) {
            const ulonglong2* bp = (const ulonglong2*)(sB + cBase);
            ulonglong2 t0 = bp[0], t1 = bp[1];
            bb[0] = t0.x; bb[1] = t0.y; bb[2] = t1.x; bb[3] = t1.y;
            first = false;
        }

        if (t + stride < nTiles) stage((t + stride) * TE, buf ^ 1);

        // in-smem affine+relu transform
        {
            float4* bufp = sIn4 + buf * BUF;
            const float4* sc4 = (const float4*)sScale;
            const float4* sh4 = (const float4*)sShift;
            for (int idx = tid; idx < TE * Kv4; idx += 128) {
                int e = idx >> 4;
                int kq = idx & 15;
                float4 v = bufp[e * Kv4p + kq];
                float4 sc = sc4[kq], sh = sh4[kq];
                v.x = fmaxf(fmaf(v.x, sc.x, sh.x), 0.f);
                v.y = fmaxf(fmaf(v.y, sc.y, sh.y), 0.f);
                v.z = fmaxf(fmaf(v.z, sc.z, sh.z), 0.f);
                v.w = fmaxf(fmaf(v.w, sc.w, sh.w), 0.f);
                bufp[e * Kv4p + kq] = v;
            }
            __syncthreads();
        }

        const float4* bufp = sIn4 + buf * BUF;
        const int base = t * TE;

        u64 acc[8][4];
#pragma unroll
        for (int i = 0; i < 8; i++) {
            acc[i][0] = bb[0]; acc[i][1] = bb[1]; acc[i][2] = bb[2]; acc[i][3] = bb[3];
        }

#pragma unroll 1
        for (int kq = 0; kq < Kv4; kq++) {
            float4 a4[8];
#pragma unroll
            for (int i = 0; i < 8; i++)
                a4[i] = bufp[(band + elane + (i << 2)) * Kv4p + kq];
#pragma unroll
            for (int kr = 0; kr < 4; kr++) {
                const int k = kq * 4 + kr;
                const ulonglong2* wp = (const ulonglong2*)(sW + k * 64 + cBase);
                ulonglong2 w01 = wp[0];
                ulonglong2 w23 = wp[1];
#pragma unroll
                for (int i = 0; i < 8; i++) {
                    float av = (kr == 0) ? a4[i].x : (kr == 1) ? a4[i].y
                             : (kr == 2) ? a4[i].z : a4[i].w;
                    u64 ap = pack2(av, av);
                    ffma2(acc[i][0], ap, w01.x);
                    ffma2(acc[i][1], ap, w01.y);
                    ffma2(acc[i][2], ap, w23.x);
                    ffma2(acc[i][3], ap, w23.y);
                }
            }
        }

#pragma unroll
        for (int i = 0; i < 8; i++) {
            int e = band + elane + (i << 2);
            int ge = base + e;
            if (ge < M) {
                ulonglong2* o = (ulonglong2*)(out + (size_t)ge * Dd + cBase);
                ulonglong2 s0; s0.x = acc[i][0]; s0.y = acc[i][1];
                ulonglong2 s1; s1.x = acc[i][2]; s1.y = acc[i][3];
                o[0] = s0; o[1] = s1;
#pragma unroll
                for (int p = 0; p < 4; p++) { fadd2(ls[p], acc[i][p]); fsq2(lq[p], acc[i][p]); }
            }
        }
        buf ^= 1;
    }

    __syncthreads();
#pragma unroll
    for (int p = 0; p < 4; p++) {
        float lo, hi;
        unpack2(ls[p], lo, hi);
        atomicAdd(&sSum[cBase + 2 * p], (double)lo);
        atomicAdd(&sSum[cBase + 2 * p + 1], (double)hi);
        unpack2(lq[p], lo, hi);
        atomicAdd(&sSq[cBase + 2 * p], (double)lo);
        atomicAdd(&sSq[cBase + 2 * p + 1], (double)hi);
    }
    __syncthreads();
    if (tid < 64) {
        atomicAdd(&g_sum[tid], sSum[tid]);
        atomicAdd(&g_sumsq[tid], sSq[tid]);
    }
}

// ---------------- BN finalize ----------------
__global__ void finalize_bn_kernel(const float* __restrict__ g, const float* __restrict__ be,
                                   double invCount) {
    int c = threadIdx.x;
    if (c >= Dd) return;
    double s = g_sum[c], q = g_sumsq[c];
    double m = s * invCount;
    double var = q * invCount - m * m;
    if (var < 0.0) var = 0.0;
    float rstd = rsqrtf((float)var + EPS);
    float sc = g[c] * rstd;
    g_scale[c] = sc;
    g_shift[c] = be[c] - (float)m * sc;
    g_sum[c] = 0.0;
    g_sumsq[c] = 0.0;
}

// ---------------- zero aggr (only needed once, before layer 0) ----------------
__global__ void zero_aggr_kernel(int total4) {
    int i = blockIdx.x * blockDim.x + threadIdx.x;
    if (i < total4) ((float4*)g_aggr)[i] = make_float4(0.f, 0.f, 0.f, 0.f);
}

// ---------------- scatter: aggr[dst] += relu(affine(m2)), vectorized red ----------------
__global__ void scatter_kernel(const float* __restrict__ m, const int* __restrict__ dst,
                               const float* __restrict__ scale, const float* __restrict__ shift,
                               int E) {
    int idx = blockIdx.x * blockDim.x + threadIdx.x;
    int total = E * 4;
    if (idx >= total) return;
    int e = idx >> 2, q = idx & 3;        // q: 16-float quarter of the row
    const float4* m4 = (const float4*)m + (size_t)e * 16 + q * 4;
    const float4* sc4 = (const float4*)scale + q * 4;
    const float4* sh4 = (const float4*)shift + q * 4;
    float* a = g_aggr + (size_t)dst[e] * Dd + q * 16;
#pragma unroll
    for (int j = 0; j < 4; j++) {
        float4 v = m4[j];
        float4 sc = sc4[j], sh = sh4[j];
        float r0 = fmaxf(fmaf(v.x, sc.x, sh.x), 0.f);
        float r1 = fmaxf(fmaf(v.y, sc.y, sh.y), 0.f);
        float r2 = fmaxf(fmaf(v.z, sc.z, sh.z), 0.f);
        float r3 = fmaxf(fmaf(v.w, sc.w, sh.w), 0.f);
        asm volatile("red.global.add.v4.f32 [%0], {%1, %2, %3, %4};"
                     :: "l"(a + j * 4), "f"(r0), "f"(r1), "f"(r2), "f"(r3) : "memory");
    }
}

// ---------------- h += relu(affine(u2)); re-zero aggr for next layer; optional h emit ----------------
__global__ void h_update_kernel(const float* __restrict__ u, const float* __restrict__ scale,
                                const float* __restrict__ shift, float* __restrict__ outh,
                                int total4) {
    int i = blockIdx.x * blockDim.x + threadIdx.x;
    if (i >= total4) return;
    int q = i & 15;
    float4 v = ((const float4*)u)[i];
    float4 sc = ((const float4*)scale)[q];
    float4 sh = ((const float4*)shift)[q];
    float4 hv = ((float4*)g_h)[i];
    hv.x += fmaxf(fmaf(v.x, sc.x, sh.x), 0.f);
    hv.y += fmaxf(fmaf(v.y, sc.y, sh.y), 0.f);
    hv.z += fmaxf(fmaf(v.z, sc.z, sh.z), 0.f);
    hv.w += fmaxf(fmaf(v.w, sc.w, sh.w), 0.f);
    ((float4*)g_h)[i] = hv;
    // zero aggr for the next layer's scatter (same index space)
    ((float4*)g_aggr)[i] = make_float4(0.f, 0.f, 0.f, 0.f);
    if (outh) {   // scalar stores: outh is not 16B-aligned (d_out + 250001 floats)
        float* o = outh + (size_t)i * 4;
        o[0] = hv.x; o[1] = hv.y; o[2] = hv.z; o[3] = hv.w;
    }
}

// ---------------- column sums of h ----------------
__global__ void colsum_kernel(int N) {
    __shared__ double s[Dd];
    int tid = threadIdx.x;
    if (tid < Dd) s[tid] = 0.0;
    __syncthreads();
    int c = tid & 63;
    int rowsPerBlk = blockDim.x >> 6;
    float part = 0.f;
    for (int n = blockIdx.x * rowsPerBlk + (tid >> 6); n < N; n += gridDim.x * rowsPerBlk)
        part += g_h[(size_t)n * Dd + c];
    atomicAdd(&s[c], (double)part);
    __syncthreads();
    if (tid < Dd) atomicAdd(&g_sum[tid], s[tid]);
}

__global__ void graph_out_kernel(const float* __restrict__ gw, const float* __restrict__ gb,
                                 float* __restrict__ out, double invN) {
    __shared__ float partial[Dd];
    int c = threadIdx.x;
    if (c < Dd) {
        partial[c] = (float)(g_sum[c] * invN) * gw[c];
        g_sum[c] = 0.0;
    }
    __syncthreads();
    if (c == 0) {
        float s = 0.f;
        for (int i = 0; i < Dd; i++) s += partial[i];
        out[0] = s + gb[0];
    }
}

__global__ void node_out_kernel(const float* __restrict__ nw, const float* __restrict__ nb,
                                float* __restrict__ out, int N) {
    int idx = blockIdx.x * blockDim.x + threadIdx.x;
    if (idx >= N * 5) return;
    int n = idx / 5, o = idx - n * 5;
    float acc = nb[o];
    const float* hr = g_h + (size_t)n * Dd;
#pragma unroll 8
    for (int k = 0; k < Dd; k++) acc = fmaf(hr[k], nw[k * 5 + o], acc);
    out[idx] = acc;
}

// ---------------- host launcher ----------------
extern "C" void kernel_launch(void* const* d_in, const int* in_sizes, int n_in,
                              void* d_out, int out_size) {
    const float* x       = (const float*)d_in[0];
    const int*   ei      = (const int*)d_in[1];
    const float* eattr   = (const float*)d_in[2];
    const float* prev_h  = (const float*)d_in[3];
    const float* lin_in_w = (const float*)d_in[4];
    const float* lin_in_b = (const float*)d_in[5];
    const float* hist_w   = (const float*)d_in[6];
    const float* hist_b   = (const float*)d_in[7];
    const float* msg_w1 = (const float*)d_in[8];
    const float* msg_b1 = (const float*)d_in[9];
    const float* msg_g1 = (const float*)d_in[10];
    const float* msg_be1 = (const float*)d_in[11];
    const float* msg_w2 = (const float*)d_in[12];
    const float* msg_b2 = (const float*)d_in[13];
    const float* msg_g2 = (const float*)d_in[14];
    const float* msg_be2 = (const float*)d_in[15];
    const float* upd_w1 = (const float*)d_in[16];
    const float* upd_b1 = (const float*)d_in[17];
    const float* upd_g1 = (const float*)d_in[18];
    const float* upd_be1 = (const float*)d_in[19];
    const float* upd_w2 = (const float*)d_in[20];
    const float* upd_b2 = (const float*)d_in[21];
    const float* upd_g2 = (const float*)d_in[22];
    const float* upd_be2 = (const float*)d_in[23];
    const float* graph_w = (const float*)d_in[24];
    const float* graph_b = (const float*)d_in[25];
    const float* node_w  = (const float*)d_in[26];
    const float* node_b  = (const float*)d_in[27];

    const int N = in_sizes[0] / 11;
    const int E = in_sizes[1] / 2;
    const int* src = ei;
    const int* dst = ei + E;

    float* out = (float*)d_out;
    float* out_graph = out;
    float* out_node = out + 1;
    float* out_h = out + 1 + (size_t)N * 5;

    float *p_h, *p_aggr, *p_u, *p_m, *p_scale, *p_shift;
    cudaGetSymbolAddress((void**)&p_h, g_h);
    cudaGetSymbolAddress((void**)&p_aggr, g_aggr);
    cudaGetSymbolAddress((void**)&p_u, g_u);
    cudaGetSymbolAddress((void**)&p_m, g_m);
    cudaGetSymbolAddress((void**)&p_scale, g_scale);
    cudaGetSymbolAddress((void**)&p_shift, g_shift);

    // Template A sizes (R2): TE*(K/4+1)*16 + K*256 + 1024(stats) + 1024(idx)
    const int s132 = TE * 34 * 16 + 132 * 256 + 1024 + 1024;   // 105472
    const int s128 = TE * 33 * 16 + 128 * 256 + 1024 + 1024;   // 102400
    // Template B size (R8): 2*TE*17*16 + (64*64+192)*4 + 1024
    const int s64  = 2 * TE * 17 * 16 + (64 * 64 + 192) * 4 + 1024;   // 87808
    cudaFuncSetAttribute(gemm_bn_kernel<132, 0>, cudaFuncAttributeMaxDynamicSharedMemorySize, s132);
    cudaFuncSetAttribute(gemm_bn_kernel<128, 2>, cudaFuncAttributeMaxDynamicSharedMemorySize, s128);
    cudaFuncSetAttribute(gemm_bn_pipe_kernel,    cudaFuncAttributeMaxDynamicSharedMemorySize, s64);

    const int tilesE = (E + TE - 1) / TE;
    const int tilesN = (N + TE - 1) / TE;
    const int gE132 = tilesE < 296 ? tilesE : 296;   // 2 blocks/SM
    const int gE64  = tilesE < 296 ? tilesE : 296;
    const int gN128 = tilesN < 296 ? tilesN : 296;
    const int gN64  = tilesN < 296 ? tilesN : 296;

    const double invE = 1.0 / (double)E;
    const double invN = 1.0 / (double)N;

    init_h_kernel<<<(N * Dd + 255) / 256, 256>>>(x, prev_h, lin_in_w, lin_in_b, hist_w, hist_b, N);
    zero_aggr_kernel<<<(N * 16 + 255) / 256, 256>>>(N * 16);   // once; h_update re-zeroes after

    for (int l = 0; l < 4; l++) {
        gemm_bn_kernel<132, 0><<<gE132, 128, s132>>>(
            msg_w1 + (size_t)l * 132 * Dd, msg_b1 + l * Dd,
            p_h, eattr, dst, src, p_m, E);
        finalize_bn_kernel<<<1, 64>>>(msg_g1 + l * Dd, msg_be1 + l * Dd, invE);

        gemm_bn_pipe_kernel<<<gE64, 128, s64>>>(
            msg_w2 + (size_t)l * 64 * Dd, msg_b2 + l * Dd,
            p_m, p_scale, p_shift, p_m, E);
        finalize_bn_kernel<<<1, 64>>>(msg_g2 + l * Dd, msg_be2 + l * Dd, invE);

        scatter_kernel<<<(E * 4 + 255) / 256, 256>>>(p_m, dst, p_scale, p_shift, E);

        gemm_bn_kernel<128, 2><<<gN128, 128, s128>>>(
            upd_w1 + (size_t)l * 128 * Dd, upd_b1 + l * Dd,
            p_h, p_aggr, nullptr, nullptr, p_u, N);
        finalize_bn_kernel<<<1, 64>>>(upd_g1 + l * Dd, upd_be1 + l * Dd, invN);

        gemm_bn_pipe_kernel<<<gN64, 128, s64>>>(
            upd_w2 + (size_t)l * 64 * Dd, upd_b2 + l * Dd,
            p_u, p_scale, p_shift, p_u, N);
        finalize_bn_kernel<<<1, 64>>>(upd_g2 + l * Dd, upd_be2 + l * Dd, invN);

        // h += relu(affine(u2)); also zeroes aggr for next layer; last layer emits h
        h_update_kernel<<<(N * 16 + 255) / 256, 256>>>(
            p_u, p_scale, p_shift, (l == 3) ? out_h : (float*)nullptr, N * 16);
    }

    colsum_kernel<<<444, 256>>>(N);
    graph_out_kernel<<<1, 64>>>(graph_w, graph_b, out_graph, invN);
    node_out_kernel<<<(N * 5 + 255) / 256, 256>>>(node_w, node_b, out_node, N);
}